// round 11
// baseline (speedup 1.0000x reference)
#include <cuda_runtime.h>
#include <cuda_fp16.h>
#include <cstdint>

// Problem constants
#define B_NODES 100000
#define U_NODES 50000
#define NTOT    150000
#define F_DIM   512
#define D_DIM   128
#define K_NEIGH 10
#define KOUT    1152

#define SMEM_SWIZZLE_128B(byte_offset) ((byte_offset) ^ (((byte_offset) >> 3) & 0x70))

// ---------------------------------------------------------------------------
// Warp-level tensor-core primitives
// ---------------------------------------------------------------------------
__device__ __forceinline__ uint32_t smem_u32(const void* p) {
    uint32_t a;
    asm("{ .reg .u64 t; cvta.to.shared.u64 t, %1; cvt.u32.u64 %0, t; }" : "=r"(a) : "l"(p));
    return a;
}

__device__ __forceinline__ void ldm_x4(uint32_t* r, uint32_t addr) {
    asm volatile("ldmatrix.sync.aligned.m8n8.x4.shared.b16 {%0,%1,%2,%3}, [%4];"
        : "=r"(r[0]), "=r"(r[1]), "=r"(r[2]), "=r"(r[3]) : "r"(addr));
}

__device__ __forceinline__ void mma_f16(float* c, const uint32_t* a,
                                        uint32_t b0, uint32_t b1) {
    asm volatile("mma.sync.aligned.m16n8k16.row.col.f32.f16.f16.f32 "
        "{%0,%1,%2,%3}, {%4,%5,%6,%7}, {%8,%9}, {%0,%1,%2,%3};"
        : "+f"(c[0]), "+f"(c[1]), "+f"(c[2]), "+f"(c[3])
        : "r"(a[0]), "r"(a[1]), "r"(a[2]), "r"(a[3]), "r"(b0), "r"(b1));
}

__device__ __forceinline__ uint32_t pack_h2(float x, float y) {
    __half2 h = __float22half2_rn(make_float2(x, y));
    return *reinterpret_cast<uint32_t*>(&h);
}

__device__ __forceinline__ void cp_async16(uint32_t dst, const void* src) {
    asm volatile("cp.async.cg.shared.global [%0], [%1], 16;" :: "r"(dst), "l"(src) : "memory");
}
#define CP_ASYNC_COMMIT() asm volatile("cp.async.commit_group;" ::: "memory")
#define CP_ASYNC_WAIT0()  asm volatile("cp.async.wait_group 0;" ::: "memory")

#define STS128(a0, a1, a2, a3, addr) \
    asm volatile("st.shared.v4.b32 [%0], {%1, %2, %3, %4};" \
        :: "r"(addr), "r"(a0), "r"(a1), "r"(a2), "r"(a3) : "memory")

// ---------------------------------------------------------------------------
// Device-global scratch (device-code references only)
// ---------------------------------------------------------------------------
__device__ float g_s[NTOT];
// fp16 h for NEIGHBOR rows only (rows B..B+U), [U][128]
__device__ __align__(16) __half g_h16[(size_t)U_NODES * D_DIM];
// fp16 h' [B][128], padded so OOB cp.async in the last CTA stays in-bounds
__device__ __align__(16) __half g_hprime16[(size_t)(B_NODES + 256) * D_DIM];
// fp16 transposed weights: [N=128][K]
__device__ __align__(16) __half g_W16_1[(size_t)D_DIM * F_DIM];
__device__ __align__(16) __half g_W16_2[(size_t)D_DIM * KOUT];

// ---------------------------------------------------------------------------
// Weight transpose + fp16 rounding: src [K][128] fp32 -> dstT [128][K] fp16
// ---------------------------------------------------------------------------
template <int WHICH>   // 1 = W (K=512), 2 = Wd (K=1152)
__global__ void convertW_kernel(const float* __restrict__ src)
{
    constexpr int K = (WHICH == 1) ? F_DIM : KOUT;
    __half* dstT = (WHICH == 1) ? g_W16_1 : g_W16_2;

    int idx = blockIdx.x * blockDim.x + threadIdx.x;
    if (idx >= K * D_DIM) return;
    int k = idx >> 7, n = idx & 127;
    dstT[(size_t)n * K + k] = __float2half_rn(src[idx]);
}

// Zero the fused-s accumulator (graph-replay safe: runs every launch)
__global__ void zero_s_kernel()
{
    int i = blockIdx.x * blockDim.x + threadIdx.x;
    if (i < NTOT) g_s[i] = 0.f;
}

// ---------------------------------------------------------------------------
// Tensor-core GEMM, fp16 m16n8k16, 64x128 CTA tile, BK=64, 2-stage pipeline,
// 3 CTAs/SM (37.5% occ). Dynamic smem: 2 x (A 8KB + B 16KB) = 48KB.
// 8 warps: 2(M) x 4(N), warp tile 32x32.
// MODE 1: A=[fb;fn] K=512; FUSED epilogue: s += h.a_half (atomic), and
//         fp16 h written for neighbor rows only.
// MODE 2: A=[fb | h'16 | nf] K=1152 (h' chunks cp.async'd as fp16) -> relu out.
// ---------------------------------------------------------------------------
template <int MODE>
__global__ void __launch_bounds__(256, 3)
gemm_mma_kernel(const float* __restrict__ fb, const float* __restrict__ fn,
                const float* __restrict__ nf, const float* __restrict__ avec,
                float* __restrict__ outp)
{
    constexpr int KTOT   = (MODE == 1) ? F_DIM : KOUT;
    constexpr int NCHUNK = KTOT / 64;
    constexpr int MROWS  = (MODE == 1) ? NTOT : B_NODES;

    extern __shared__ char dsm[];
    const uint32_t ab = (smem_u32(dsm) + 1023u) & ~1023u;

    const int tid = threadIdx.x;
    const int lane = tid & 31;
    const int wn = (tid >> 5) & 3;       // 0..3  N groups of 32 cols
    const int wm = (tid >> 5) >> 2;      // 0..1  M groups of 32 rows
    const int rowBase = blockIdx.x * 64;

    const __half* BT = (MODE == 1) ? g_W16_1 : g_W16_2;

    float acc[2][4][4];
    #pragma unroll
    for (int i = 0; i < 2; ++i)
        #pragma unroll
        for (int j = 0; j < 4; ++j)
            #pragma unroll
            for (int q = 0; q < 4; ++q) acc[i][j][q] = 0.f;

    const int lr = lane & 7;
    const int lg = lane >> 3;

    // per-thread A staging: 2 iters x 8 floats (tile 64 rows x 64 fp32)
    float4 sa0[2], sa1[2];

    // fp16-direct A chunk? (GEMM2's h' region, k in [512,640))
    auto isF16chunk = [&](int c) { return MODE == 2 && c >= 8 && c < 10; };

    auto aSrc = [&](int grow, int k0c) -> const float* {
        if (MODE == 1) {
            return (grow < B_NODES) ? fb + (size_t)grow * F_DIM + k0c
                                    : fn + (size_t)(grow - B_NODES) * F_DIM + k0c;
        } else {
            if (k0c < 512) return fb + (size_t)grow * F_DIM + k0c;
            else           return nf + (size_t)grow * F_DIM + (k0c - 640);
        }
    };

    auto issueLoads = [&](int c, uint32_t stageA, uint32_t stageB) {
        const int k0c = c * 64;
        if (isF16chunk(c)) {
            // A tile (64 rows x 128B) already fp16 in g_hprime16 (padded)
            #pragma unroll
            for (int i = 0; i < 2; ++i) {
                int idx = tid + i * 256;            // 0..511
                int row = idx >> 3, seg = idx & 7;
                int grow = rowBase + row;           // pad covers OOB
                uint32_t off = SMEM_SWIZZLE_128B((uint32_t)(row * 128 + seg * 16));
                cp_async16(stageA + off,
                           g_hprime16 + (size_t)grow * D_DIM + (k0c - 512) + seg * 8);
            }
        } else {
            #pragma unroll
            for (int i = 0; i < 2; ++i) {
                int idx = tid + i * 256;            // 0..511
                int row = idx >> 3, seg = idx & 7;  // 64 rows x 8 segs of 8 f32
                int grow = rowBase + row;
                sa0[i] = make_float4(0.f, 0.f, 0.f, 0.f);
                sa1[i] = sa0[i];
                if (grow < MROWS) {
                    const float* src = aSrc(grow, k0c) + seg * 8;
                    sa0[i] = *(const float4*)(src);
                    sa1[i] = *(const float4*)(src + 4);
                }
            }
        }
        #pragma unroll
        for (int i = 0; i < 4; ++i) {
            int idx = tid + i * 256;                // 0..1023
            int row = idx >> 3, seg = idx & 7;      // 128 n-rows x 8 segs
            uint32_t off = SMEM_SWIZZLE_128B((uint32_t)(row * 128 + seg * 16));
            cp_async16(stageB + off, BT + (size_t)row * KTOT + k0c + seg * 8);
        }
        CP_ASYNC_COMMIT();
    };

    auto commitLoads = [&](int c, uint32_t stageA) {
        if (!isF16chunk(c)) {
            #pragma unroll
            for (int i = 0; i < 2; ++i) {
                int idx = tid + i * 256;
                int row = idx >> 3, seg = idx & 7;
                uint32_t w0 = pack_h2(sa0[i].x, sa0[i].y);
                uint32_t w1 = pack_h2(sa0[i].z, sa0[i].w);
                uint32_t w2 = pack_h2(sa1[i].x, sa1[i].y);
                uint32_t w3 = pack_h2(sa1[i].z, sa1[i].w);
                uint32_t off = SMEM_SWIZZLE_128B((uint32_t)(row * 128 + seg * 16));
                STS128(w0, w1, w2, w3, stageA + off);
            }
        }
        CP_ASYNC_WAIT0();
    };

    auto computeChunk = [&](uint32_t stageA, uint32_t stageB) {
        #pragma unroll
        for (int t = 0; t < 4; ++t) {
            uint32_t af[2][4];
            #pragma unroll
            for (int i = 0; i < 2; ++i) {
                int row = wm * 32 + i * 16 + lr + (lg & 1) * 8;   // <= 63
                int kb = t * 32 + (lg >> 1) * 16;
                ldm_x4(af[i], stageA + SMEM_SWIZZLE_128B((uint32_t)(row * 128 + kb)));
            }
            uint32_t bfr[2][4];
            #pragma unroll
            for (int j = 0; j < 2; ++j) {
                int row = wn * 32 + j * 16 + lr + (lg >> 1) * 8;  // <= 127
                int kb = t * 32 + (lg & 1) * 16;
                ldm_x4(bfr[j], stageB + SMEM_SWIZZLE_128B((uint32_t)(row * 128 + kb)));
            }
            #pragma unroll
            for (int i = 0; i < 2; ++i)
                #pragma unroll
                for (int j = 0; j < 2; ++j) {
                    mma_f16(acc[i][2 * j],     af[i], bfr[j][0], bfr[j][1]);
                    mma_f16(acc[i][2 * j + 1], af[i], bfr[j][2], bfr[j][3]);
                }
        }
    };

    auto stA = [&](int s) { return ab + (uint32_t)s * 24576u; };
    auto stB = [&](int s) { return ab + (uint32_t)s * 24576u + 8192u; };

    issueLoads(0, stA(0), stB(0));
    commitLoads(0, stA(0));
    __syncthreads();

    for (int c = 0; c < NCHUNK; ++c) {
        const int cur = c & 1, nxt = (c + 1) & 1;
        if (c + 1 < NCHUNK) issueLoads(c + 1, stA(nxt), stB(nxt));
        computeChunk(stA(cur), stB(cur));
        if (c + 1 < NCHUNK) commitLoads(c + 1, stA(nxt));
        __syncthreads();
    }

    // ---- epilogue ----
    const int qm = lane >> 2;
    const int qn = (lane & 3) * 2;

    if (MODE == 1) {
        // Fused: s[r] += h[r,:].a_half(r); write fp16 h for neighbor rows.
        #pragma unroll
        for (int i = 0; i < 2; ++i) {
            int m0 = rowBase + wm * 32 + i * 16;
            int r0 = m0 + qm, r1 = m0 + 8 + qm;
            const float* av0 = (r0 < B_NODES) ? avec : avec + D_DIM;
            const float* av1 = (r1 < B_NODES) ? avec : avec + D_DIM;
            float s0 = 0.f, s1 = 0.f;
            #pragma unroll
            for (int j = 0; j < 4; ++j) {
                int n = wn * 32 + j * 8 + qn;
                float c0 = acc[i][j][0], c1 = acc[i][j][1];
                float c2 = acc[i][j][2], c3 = acc[i][j][3];
                s0 += c0 * av0[n] + c1 * av0[n + 1];
                s1 += c2 * av1[n] + c3 * av1[n + 1];
                if (r0 >= B_NODES && r0 < NTOT) {
                    __half2 h = __float22half2_rn(make_float2(c0, c1));
                    *(__half2*)(g_h16 + (size_t)(r0 - B_NODES) * D_DIM + n) = h;
                }
                if (r1 >= B_NODES && r1 < NTOT) {
                    __half2 h = __float22half2_rn(make_float2(c2, c3));
                    *(__half2*)(g_h16 + (size_t)(r1 - B_NODES) * D_DIM + n) = h;
                }
            }
            // quad reduction (lanes within a quad share the same row)
            s0 += __shfl_xor_sync(0xffffffffu, s0, 1);
            s0 += __shfl_xor_sync(0xffffffffu, s0, 2);
            s1 += __shfl_xor_sync(0xffffffffu, s1, 1);
            s1 += __shfl_xor_sync(0xffffffffu, s1, 2);
            if ((lane & 3) == 0) {
                if (r0 < NTOT) atomicAdd(&g_s[r0], s0);
                if (r1 < NTOT) atomicAdd(&g_s[r1], s1);
            }
        }
    } else {
        #pragma unroll
        for (int i = 0; i < 2; ++i) {
            #pragma unroll
            for (int j = 0; j < 4; ++j) {
                int m0 = rowBase + wm * 32 + i * 16;
                int n  = wn * 32 + j * 8 + qn;
                float c0 = fmaxf(acc[i][j][0], 0.f), c1 = fmaxf(acc[i][j][1], 0.f);
                float c2 = fmaxf(acc[i][j][2], 0.f), c3 = fmaxf(acc[i][j][3], 0.f);
                int r0 = m0 + qm, r1 = m0 + 8 + qm;
                if (r0 < MROWS) *(float2*)(outp + (size_t)r0 * D_DIM + n) = make_float2(c0, c1);
                if (r1 < MROWS) *(float2*)(outp + (size_t)r1 * D_DIM + n) = make_float2(c2, c3);
            }
        }
    }
}

// ---------------------------------------------------------------------------
// Aggregation: one block per batch node; thread t owns feature column t.
// Reads fp16 h (neighbor rows), writes fp16 h'.
// ---------------------------------------------------------------------------
__global__ void __launch_bounds__(128) agg_kernel(const int* __restrict__ edge_dst)
{
    const int i = blockIdx.x;
    const int t = threadIdx.x;
    __shared__ float w[K_NEIGH];
    __shared__ int   jj[K_NEIGH];
    if (t < K_NEIGH) {
        int j = edge_dst[(size_t)i * K_NEIGH + t];
        float sc = g_s[i] + g_s[B_NODES + j];
        float lr = sc > 0.f ? sc : 0.2f * sc;   // leaky_relu, alpha=0.2
        w[t]  = expf(-lr);
        jj[t] = j;
    }
    __syncthreads();
    float tot = 0.f, acc = 0.f;
    #pragma unroll
    for (int k = 0; k < K_NEIGH; ++k) {
        float wk = w[k];
        tot += wk;
        acc += wk * __half2float(g_h16[(size_t)jj[k] * D_DIM + t]);
    }
    float v = acc / tot;
    if (!isfinite(v)) v = 0.f;   // nan_to_num guard
    g_hprime16[(size_t)i * D_DIM + t] = __float2half_rn(v);
}

// ---------------------------------------------------------------------------
// Launch
// Inputs: 0=feats_batch 1=feats_neigh 2=neigh_feats 3=W 4=a 5=Wd 6=edge_src 7=edge_dst
// ---------------------------------------------------------------------------
extern "C" void kernel_launch(void* const* d_in, const int* in_sizes, int n_in,
                              void* d_out, int out_size)
{
    const float* fb   = (const float*)d_in[0];
    const float* fn   = (const float*)d_in[1];
    const float* nf   = (const float*)d_in[2];
    const float* W    = (const float*)d_in[3];
    const float* avec = (const float*)d_in[4];
    const float* Wd   = (const float*)d_in[5];
    const int* edge_dst = (const int*)d_in[7];
    float* out = (float*)d_out;
    (void)in_sizes; (void)n_in; (void)out_size;

    const int SMEM_BYTES = 50176;  // 2 x 24KB stages + 1KB align slack
    cudaFuncSetAttribute(gemm_mma_kernel<1>, cudaFuncAttributeMaxDynamicSharedMemorySize, SMEM_BYTES);
    cudaFuncSetAttribute(gemm_mma_kernel<2>, cudaFuncAttributeMaxDynamicSharedMemorySize, SMEM_BYTES);

    // 0) fp16-round + transpose weights; zero fused-s accumulator
    convertW_kernel<1><<<(F_DIM * D_DIM + 255) / 256, 256>>>(W);
    convertW_kernel<2><<<(KOUT * D_DIM + 255) / 256, 256>>>(Wd);
    zero_s_kernel<<<(NTOT + 255) / 256, 256>>>();

    // 1) h = [fb; fn] @ W  (fused: s accumulation + fp16 neighbor-h write)
    gemm_mma_kernel<1><<<(NTOT + 63) / 64, 256, SMEM_BYTES>>>(fb, fn, nullptr, avec, nullptr);

    // 2) per-node weighted aggregation -> fp16 h'
    agg_kernel<<<B_NODES, 128>>>(edge_dst);

    // 3) out = relu([fb | h' | nf] @ Wd)
    gemm_mma_kernel<2><<<(B_NODES + 63) / 64, 256, SMEM_BYTES>>>(fb, nullptr, nf, nullptr, out);
}

// round 12
// speedup vs baseline: 1.0079x; 1.0079x over previous
#include <cuda_runtime.h>
#include <cuda_fp16.h>
#include <cstdint>

// Problem constants
#define B_NODES 100000
#define U_NODES 50000
#define NTOT    150000
#define F_DIM   512
#define D_DIM   128
#define K_NEIGH 10
#define KOUT    1152

#define SMEM_SWIZZLE_128B(byte_offset) ((byte_offset) ^ (((byte_offset) >> 3) & 0x70))

// ---------------------------------------------------------------------------
// Warp-level tensor-core primitives
// ---------------------------------------------------------------------------
__device__ __forceinline__ uint32_t smem_u32(const void* p) {
    uint32_t a;
    asm("{ .reg .u64 t; cvta.to.shared.u64 t, %1; cvt.u32.u64 %0, t; }" : "=r"(a) : "l"(p));
    return a;
}

__device__ __forceinline__ void ldm_x4(uint32_t* r, uint32_t addr) {
    asm volatile("ldmatrix.sync.aligned.m8n8.x4.shared.b16 {%0,%1,%2,%3}, [%4];"
        : "=r"(r[0]), "=r"(r[1]), "=r"(r[2]), "=r"(r[3]) : "r"(addr));
}

__device__ __forceinline__ void mma_f16(float* c, const uint32_t* a,
                                        uint32_t b0, uint32_t b1) {
    asm volatile("mma.sync.aligned.m16n8k16.row.col.f32.f16.f16.f32 "
        "{%0,%1,%2,%3}, {%4,%5,%6,%7}, {%8,%9}, {%0,%1,%2,%3};"
        : "+f"(c[0]), "+f"(c[1]), "+f"(c[2]), "+f"(c[3])
        : "r"(a[0]), "r"(a[1]), "r"(a[2]), "r"(a[3]), "r"(b0), "r"(b1));
}

__device__ __forceinline__ uint32_t pack_h2(float x, float y) {
    __half2 h = __float22half2_rn(make_float2(x, y));
    return *reinterpret_cast<uint32_t*>(&h);
}

__device__ __forceinline__ void cp_async16(uint32_t dst, const void* src) {
    asm volatile("cp.async.cg.shared.global [%0], [%1], 16;" :: "r"(dst), "l"(src) : "memory");
}
#define CP_ASYNC_COMMIT() asm volatile("cp.async.commit_group;" ::: "memory")
#define CP_ASYNC_WAIT0()  asm volatile("cp.async.wait_group 0;" ::: "memory")

#define STS128(a0, a1, a2, a3, addr) \
    asm volatile("st.shared.v4.b32 [%0], {%1, %2, %3, %4};" \
        :: "r"(addr), "r"(a0), "r"(a1), "r"(a2), "r"(a3) : "memory")

// ---------------------------------------------------------------------------
// Device-global scratch (device-code references only)
// ---------------------------------------------------------------------------
__device__ float g_s[NTOT];
// fp16 h for NEIGHBOR rows only, [U][128]
__device__ __align__(16) __half g_h16[(size_t)U_NODES * D_DIM];
// fp16 h' [B+pad][128] (pad covers cp.async OOB rows in last GEMM2 CTA)
__device__ __align__(16) __half g_hprime16[(size_t)(B_NODES + 256) * D_DIM];
// fp16 partial = fb @ Wd[0:512]  [B][128]
__device__ __align__(16) __half g_partial16[(size_t)B_NODES * D_DIM];
// fp16 transposed weights: [N=128][K]
__device__ __align__(16) __half g_W16_1[(size_t)D_DIM * F_DIM];
__device__ __align__(16) __half g_W16_2[(size_t)D_DIM * KOUT];

// ---------------------------------------------------------------------------
// Weight transpose + fp16 rounding: src [K][128] fp32 -> dstT [128][K] fp16
// ---------------------------------------------------------------------------
template <int WHICH>   // 1 = W (K=512), 2 = Wd (K=1152)
__global__ void convertW_kernel(const float* __restrict__ src)
{
    constexpr int K = (WHICH == 1) ? F_DIM : KOUT;
    __half* dstT = (WHICH == 1) ? g_W16_1 : g_W16_2;

    int idx = blockIdx.x * blockDim.x + threadIdx.x;
    if (idx >= K * D_DIM) return;
    int k = idx >> 7, n = idx & 127;
    dstT[(size_t)n * K + k] = __float2half_rn(src[idx]);
}

// Zero the fused-s accumulator (graph-replay safe)
__global__ void zero_s_kernel()
{
    int i = blockIdx.x * blockDim.x + threadIdx.x;
    if (i < NTOT) g_s[i] = 0.f;
}

// ---------------------------------------------------------------------------
// FUSED kernel over fb rows: 64-row CTA tile, K=512, BK=64, 2-stage pipeline.
// Warp specialization: warps 0-3 compute h = fb@W (only to produce s, never
// stored); warps 4-7 compute partial = fb@Wd[0:512] -> fp16 store.
// smem/stage = A 8KB + B_W 16KB + B_Wd 16KB = 40KB; 2 stages = 80KB; 2 CTA/SM.
// Each product: 4 warps in 2(M)x2(N), warp tile 32x64, acc 64 regs.
// ---------------------------------------------------------------------------
__global__ void __launch_bounds__(256, 2)
fused_fb_kernel(const float* __restrict__ fb, const float* __restrict__ avec)
{
    constexpr int NCHUNK = F_DIM / 64;   // 8

    extern __shared__ char dsm[];
    const uint32_t ab = (smem_u32(dsm) + 1023u) & ~1023u;

    const int tid = threadIdx.x;
    const int lane = tid & 31;
    const int wid = tid >> 5;
    const int prod = wid >> 2;           // 0 = W product, 1 = Wd product
    const int w2 = wid & 3;
    const int wm = w2 & 1;               // M group (2 x 32 rows)
    const int wn = w2 >> 1;              // N group (2 x 64 cols)
    const int rowBase = blockIdx.x * 64;

    float acc[2][8][4];
    #pragma unroll
    for (int i = 0; i < 2; ++i)
        #pragma unroll
        for (int j = 0; j < 8; ++j)
            #pragma unroll
            for (int q = 0; q < 4; ++q) acc[i][j][q] = 0.f;

    const int lr = lane & 7;
    const int lg = lane >> 3;

    float4 sa0[2], sa1[2];   // A staging: 64 rows x 8 segs = 512 tasks / 256 thr

    auto stA   = [&](int s) { return ab + (uint32_t)s * 40960u; };
    auto stBW  = [&](int s) { return ab + (uint32_t)s * 40960u + 8192u; };
    auto stBWd = [&](int s) { return ab + (uint32_t)s * 40960u + 24576u; };

    auto issueLoads = [&](int c, int s) {
        const int k0c = c * 64;
        #pragma unroll
        for (int i = 0; i < 2; ++i) {
            int idx = tid + i * 256;           // 0..511
            int row = idx >> 3, seg = idx & 7;
            int grow = rowBase + row;
            sa0[i] = make_float4(0.f, 0.f, 0.f, 0.f);
            sa1[i] = sa0[i];
            if (grow < B_NODES) {
                const float* src = fb + (size_t)grow * F_DIM + k0c + seg * 8;
                sa0[i] = *(const float4*)(src);
                sa1[i] = *(const float4*)(src + 4);
            }
        }
        #pragma unroll
        for (int i = 0; i < 4; ++i) {
            int idx = tid + i * 256;           // 0..1023
            int row = idx >> 3, seg = idx & 7; // 128 n-rows x 8 segs
            uint32_t off = SMEM_SWIZZLE_128B((uint32_t)(row * 128 + seg * 16));
            cp_async16(stBW(s) + off,  g_W16_1 + (size_t)row * F_DIM + k0c + seg * 8);
            cp_async16(stBWd(s) + off, g_W16_2 + (size_t)row * KOUT  + k0c + seg * 8);
        }
        CP_ASYNC_COMMIT();
    };

    auto commitLoads = [&](int s) {
        #pragma unroll
        for (int i = 0; i < 2; ++i) {
            int idx = tid + i * 256;
            int row = idx >> 3, seg = idx & 7;
            uint32_t w0 = pack_h2(sa0[i].x, sa0[i].y);
            uint32_t w1 = pack_h2(sa0[i].z, sa0[i].w);
            uint32_t w2r = pack_h2(sa1[i].x, sa1[i].y);
            uint32_t w3 = pack_h2(sa1[i].z, sa1[i].w);
            uint32_t off = SMEM_SWIZZLE_128B((uint32_t)(row * 128 + seg * 16));
            STS128(w0, w1, w2r, w3, stA(s) + off);
        }
        CP_ASYNC_WAIT0();
    };

    auto computeChunk = [&](int s) {
        const uint32_t sA = stA(s);
        const uint32_t sB = prod ? stBWd(s) : stBW(s);
        #pragma unroll
        for (int t = 0; t < 4; ++t) {
            uint32_t af[2][4];
            #pragma unroll
            for (int i = 0; i < 2; ++i) {
                int row = wm * 32 + i * 16 + lr + (lg & 1) * 8;   // <= 63
                int kb = t * 32 + (lg >> 1) * 16;
                ldm_x4(af[i], sA + SMEM_SWIZZLE_128B((uint32_t)(row * 128 + kb)));
            }
            uint32_t bfr[4][4];
            #pragma unroll
            for (int j = 0; j < 4; ++j) {
                int row = wn * 64 + j * 16 + lr + (lg >> 1) * 8;  // <= 127
                int kb = t * 32 + (lg & 1) * 16;
                ldm_x4(bfr[j], sB + SMEM_SWIZZLE_128B((uint32_t)(row * 128 + kb)));
            }
            #pragma unroll
            for (int i = 0; i < 2; ++i)
                #pragma unroll
                for (int j = 0; j < 4; ++j) {
                    mma_f16(acc[i][2 * j],     af[i], bfr[j][0], bfr[j][1]);
                    mma_f16(acc[i][2 * j + 1], af[i], bfr[j][2], bfr[j][3]);
                }
        }
    };

    issueLoads(0, 0);
    commitLoads(0);
    __syncthreads();

    for (int c = 0; c < NCHUNK; ++c) {
        const int cur = c & 1, nxt = (c + 1) & 1;
        if (c + 1 < NCHUNK) issueLoads(c + 1, nxt);
        computeChunk(cur);
        if (c + 1 < NCHUNK) commitLoads(nxt);
        __syncthreads();
    }

    // ---- epilogue ----
    const int qm = lane >> 2;
    const int qn = (lane & 3) * 2;

    if (prod == 0) {
        // s[r] += h[r,:].a[0:128]  (fb rows always use first half of a)
        #pragma unroll
        for (int i = 0; i < 2; ++i) {
            int m0 = rowBase + wm * 32 + i * 16;
            int r0 = m0 + qm, r1 = m0 + 8 + qm;
            float s0 = 0.f, s1 = 0.f;
            #pragma unroll
            for (int j = 0; j < 8; ++j) {
                int n = wn * 64 + j * 8 + qn;
                s0 += acc[i][j][0] * avec[n] + acc[i][j][1] * avec[n + 1];
                s1 += acc[i][j][2] * avec[n] + acc[i][j][3] * avec[n + 1];
            }
            s0 += __shfl_xor_sync(0xffffffffu, s0, 1);
            s0 += __shfl_xor_sync(0xffffffffu, s0, 2);
            s1 += __shfl_xor_sync(0xffffffffu, s1, 1);
            s1 += __shfl_xor_sync(0xffffffffu, s1, 2);
            if ((lane & 3) == 0) {
                if (r0 < B_NODES) atomicAdd(&g_s[r0], s0);
                if (r1 < B_NODES) atomicAdd(&g_s[r1], s1);
            }
        }
    } else {
        // partial16[r, n] = fp16(acc)
        #pragma unroll
        for (int i = 0; i < 2; ++i) {
            #pragma unroll
            for (int j = 0; j < 8; ++j) {
                int m0 = rowBase + wm * 32 + i * 16;
                int n  = wn * 64 + j * 8 + qn;
                int r0 = m0 + qm, r1 = m0 + 8 + qm;
                if (r0 < B_NODES) {
                    __half2 h = __float22half2_rn(make_float2(acc[i][j][0], acc[i][j][1]));
                    *(__half2*)(g_partial16 + (size_t)r0 * D_DIM + n) = h;
                }
                if (r1 < B_NODES) {
                    __half2 h = __float22half2_rn(make_float2(acc[i][j][2], acc[i][j][3]));
                    *(__half2*)(g_partial16 + (size_t)r1 * D_DIM + n) = h;
                }
            }
        }
    }
}

// ---------------------------------------------------------------------------
// Neighbor-rows GEMM: h = fn @ W (128x128 CTA tile, BK=64, round-10 config).
// Fused epilogue: s[B+r] += h.a[128:256] and fp16 h write.
// ---------------------------------------------------------------------------
__global__ void __launch_bounds__(256, 2)
neigh_kernel(const float* __restrict__ fn, const float* __restrict__ avec)
{
    constexpr int NCHUNK = F_DIM / 64;   // 8

    extern __shared__ char dsm[];
    const uint32_t ab = (smem_u32(dsm) + 1023u) & ~1023u;

    const int tid = threadIdx.x;
    const int lane = tid & 31;
    const int wm = (tid >> 5) & 3;
    const int wn = (tid >> 5) >> 2;
    const int rowBase = blockIdx.x * 128;

    float acc[2][8][4];
    #pragma unroll
    for (int i = 0; i < 2; ++i)
        #pragma unroll
        for (int j = 0; j < 8; ++j)
            #pragma unroll
            for (int q = 0; q < 4; ++q) acc[i][j][q] = 0.f;

    const int lr = lane & 7;
    const int lg = lane >> 3;

    float4 sa0[4], sa1[4];

    auto stA = [&](int s) { return ab + (uint32_t)s * 32768u; };
    auto stB = [&](int s) { return ab + (uint32_t)s * 32768u + 16384u; };

    auto issueLoads = [&](int c, int s) {
        const int k0c = c * 64;
        #pragma unroll
        for (int i = 0; i < 4; ++i) {
            int idx = tid + i * 256;
            int row = idx >> 3, seg = idx & 7;
            int grow = rowBase + row;
            sa0[i] = make_float4(0.f, 0.f, 0.f, 0.f);
            sa1[i] = sa0[i];
            if (grow < U_NODES) {
                const float* src = fn + (size_t)grow * F_DIM + k0c + seg * 8;
                sa0[i] = *(const float4*)(src);
                sa1[i] = *(const float4*)(src + 4);
            }
        }
        #pragma unroll
        for (int i = 0; i < 4; ++i) {
            int idx = tid + i * 256;
            int row = idx >> 3, seg = idx & 7;
            uint32_t off = SMEM_SWIZZLE_128B((uint32_t)(row * 128 + seg * 16));
            cp_async16(stB(s) + off, g_W16_1 + (size_t)row * F_DIM + k0c + seg * 8);
        }
        CP_ASYNC_COMMIT();
    };

    auto commitLoads = [&](int s) {
        #pragma unroll
        for (int i = 0; i < 4; ++i) {
            int idx = tid + i * 256;
            int row = idx >> 3, seg = idx & 7;
            uint32_t w0 = pack_h2(sa0[i].x, sa0[i].y);
            uint32_t w1 = pack_h2(sa0[i].z, sa0[i].w);
            uint32_t w2 = pack_h2(sa1[i].x, sa1[i].y);
            uint32_t w3 = pack_h2(sa1[i].z, sa1[i].w);
            uint32_t off = SMEM_SWIZZLE_128B((uint32_t)(row * 128 + seg * 16));
            STS128(w0, w1, w2, w3, stA(s) + off);
        }
        CP_ASYNC_WAIT0();
    };

    auto computeChunk = [&](int s) {
        #pragma unroll
        for (int t = 0; t < 4; ++t) {
            uint32_t af[2][4];
            #pragma unroll
            for (int i = 0; i < 2; ++i) {
                int row = wm * 32 + i * 16 + lr + (lg & 1) * 8;
                int kb = t * 32 + (lg >> 1) * 16;
                ldm_x4(af[i], stA(s) + SMEM_SWIZZLE_128B((uint32_t)(row * 128 + kb)));
            }
            uint32_t bfr[4][4];
            #pragma unroll
            for (int j = 0; j < 4; ++j) {
                int row = wn * 64 + j * 16 + lr + (lg >> 1) * 8;
                int kb = t * 32 + (lg & 1) * 16;
                ldm_x4(bfr[j], stB(s) + SMEM_SWIZZLE_128B((uint32_t)(row * 128 + kb)));
            }
            #pragma unroll
            for (int i = 0; i < 2; ++i)
                #pragma unroll
                for (int j = 0; j < 4; ++j) {
                    mma_f16(acc[i][2 * j],     af[i], bfr[j][0], bfr[j][1]);
                    mma_f16(acc[i][2 * j + 1], af[i], bfr[j][2], bfr[j][3]);
                }
        }
    };

    issueLoads(0, 0);
    commitLoads(0);
    __syncthreads();

    for (int c = 0; c < NCHUNK; ++c) {
        const int cur = c & 1, nxt = (c + 1) & 1;
        if (c + 1 < NCHUNK) issueLoads(c + 1, nxt);
        computeChunk(cur);
        if (c + 1 < NCHUNK) commitLoads(nxt);
        __syncthreads();
    }

    // ---- epilogue: s (second a-half) + fp16 h ----
    const int qm = lane >> 2;
    const int qn = (lane & 3) * 2;
    const float* av = avec + D_DIM;

    #pragma unroll
    for (int i = 0; i < 2; ++i) {
        int m0 = rowBase + wm * 32 + i * 16;
        int r0 = m0 + qm, r1 = m0 + 8 + qm;   // neighbor-local row index
        float s0 = 0.f, s1 = 0.f;
        #pragma unroll
        for (int j = 0; j < 8; ++j) {
            int n = wn * 64 + j * 8 + qn;
            float c0 = acc[i][j][0], c1 = acc[i][j][1];
            float c2 = acc[i][j][2], c3 = acc[i][j][3];
            s0 += c0 * av[n] + c1 * av[n + 1];
            s1 += c2 * av[n] + c3 * av[n + 1];
            if (r0 < U_NODES) {
                __half2 h = __float22half2_rn(make_float2(c0, c1));
                *(__half2*)(g_h16 + (size_t)r0 * D_DIM + n) = h;
            }
            if (r1 < U_NODES) {
                __half2 h = __float22half2_rn(make_float2(c2, c3));
                *(__half2*)(g_h16 + (size_t)r1 * D_DIM + n) = h;
            }
        }
        s0 += __shfl_xor_sync(0xffffffffu, s0, 1);
        s0 += __shfl_xor_sync(0xffffffffu, s0, 2);
        s1 += __shfl_xor_sync(0xffffffffu, s1, 1);
        s1 += __shfl_xor_sync(0xffffffffu, s1, 2);
        if ((lane & 3) == 0) {
            if (r0 < U_NODES) atomicAdd(&g_s[B_NODES + r0], s0);
            if (r1 < U_NODES) atomicAdd(&g_s[B_NODES + r1], s1);
        }
    }
}

// ---------------------------------------------------------------------------
// Aggregation: one block per batch node; thread t owns feature column t.
// ---------------------------------------------------------------------------
__global__ void __launch_bounds__(128) agg_kernel(const int* __restrict__ edge_dst)
{
    const int i = blockIdx.x;
    const int t = threadIdx.x;
    __shared__ float w[K_NEIGH];
    __shared__ int   jj[K_NEIGH];
    if (t < K_NEIGH) {
        int j = edge_dst[(size_t)i * K_NEIGH + t];
        float sc = g_s[i] + g_s[B_NODES + j];
        float lr = sc > 0.f ? sc : 0.2f * sc;   // leaky_relu, alpha=0.2
        w[t]  = expf(-lr);
        jj[t] = j;
    }
    __syncthreads();
    float tot = 0.f, acc = 0.f;
    #pragma unroll
    for (int k = 0; k < K_NEIGH; ++k) {
        float wk = w[k];
        tot += wk;
        acc += wk * __half2float(g_h16[(size_t)jj[k] * D_DIM + t]);
    }
    float v = acc / tot;
    if (!isfinite(v)) v = 0.f;   // nan_to_num guard
    g_hprime16[(size_t)i * D_DIM + t] = __float2half_rn(v);
}

// ---------------------------------------------------------------------------
// GEMM2': out = relu(partial + [h'|nf] @ Wd[512:1152])  (K=640, 10 chunks)
// 128x128 CTA tile, BK=64, 2-stage, 2 CTA/SM. Chunks 0-1 = h' (fp16 direct),
// chunks 2-9 = nf (fp32 -> fp16 convert).
// ---------------------------------------------------------------------------
__global__ void __launch_bounds__(256, 2)
gemm2_kernel(const float* __restrict__ nf, float* __restrict__ outp)
{
    constexpr int NCHUNK = 10;

    extern __shared__ char dsm[];
    const uint32_t ab = (smem_u32(dsm) + 1023u) & ~1023u;

    const int tid = threadIdx.x;
    const int lane = tid & 31;
    const int wm = (tid >> 5) & 3;
    const int wn = (tid >> 5) >> 2;
    const int rowBase = blockIdx.x * 128;

    float acc[2][8][4];
    #pragma unroll
    for (int i = 0; i < 2; ++i)
        #pragma unroll
        for (int j = 0; j < 8; ++j)
            #pragma unroll
            for (int q = 0; q < 4; ++q) acc[i][j][q] = 0.f;

    const int lr = lane & 7;
    const int lg = lane >> 3;

    float4 sa0[4], sa1[4];

    auto stA = [&](int s) { return ab + (uint32_t)s * 32768u; };
    auto stB = [&](int s) { return ab + (uint32_t)s * 32768u + 16384u; };

    auto issueLoads = [&](int c, int s) {
        const int k0 = 512 + c * 64;    // global k into Wd
        if (c < 2) {
            // h' fp16 direct (padded buffer covers OOB rows)
            #pragma unroll
            for (int i = 0; i < 4; ++i) {
                int idx = tid + i * 256;
                int row = idx >> 3, seg = idx & 7;
                int grow = rowBase + row;
                uint32_t off = SMEM_SWIZZLE_128B((uint32_t)(row * 128 + seg * 16));
                cp_async16(stA(s) + off,
                           g_hprime16 + (size_t)grow * D_DIM + (k0 - 512) + seg * 8);
            }
        } else {
            #pragma unroll
            for (int i = 0; i < 4; ++i) {
                int idx = tid + i * 256;
                int row = idx >> 3, seg = idx & 7;
                int grow = rowBase + row;
                sa0[i] = make_float4(0.f, 0.f, 0.f, 0.f);
                sa1[i] = sa0[i];
                if (grow < B_NODES) {
                    const float* src = nf + (size_t)grow * F_DIM + (k0 - 640) + seg * 8;
                    sa0[i] = *(const float4*)(src);
                    sa1[i] = *(const float4*)(src + 4);
                }
            }
        }
        #pragma unroll
        for (int i = 0; i < 4; ++i) {
            int idx = tid + i * 256;
            int row = idx >> 3, seg = idx & 7;
            uint32_t off = SMEM_SWIZZLE_128B((uint32_t)(row * 128 + seg * 16));
            cp_async16(stB(s) + off, g_W16_2 + (size_t)row * KOUT + k0 + seg * 8);
        }
        CP_ASYNC_COMMIT();
    };

    auto commitLoads = [&](int c, int s) {
        if (c >= 2) {
            #pragma unroll
            for (int i = 0; i < 4; ++i) {
                int idx = tid + i * 256;
                int row = idx >> 3, seg = idx & 7;
                uint32_t w0 = pack_h2(sa0[i].x, sa0[i].y);
                uint32_t w1 = pack_h2(sa0[i].z, sa0[i].w);
                uint32_t w2 = pack_h2(sa1[i].x, sa1[i].y);
                uint32_t w3 = pack_h2(sa1[i].z, sa1[i].w);
                uint32_t off = SMEM_SWIZZLE_128B((uint32_t)(row * 128 + seg * 16));
                STS128(w0, w1, w2, w3, stA(s) + off);
            }
        }
        CP_ASYNC_WAIT0();
    };

    auto computeChunk = [&](int s) {
        #pragma unroll
        for (int t = 0; t < 4; ++t) {
            uint32_t af[2][4];
            #pragma unroll
            for (int i = 0; i < 2; ++i) {
                int row = wm * 32 + i * 16 + lr + (lg & 1) * 8;
                int kb = t * 32 + (lg >> 1) * 16;
                ldm_x4(af[i], stA(s) + SMEM_SWIZZLE_128B((uint32_t)(row * 128 + kb)));
            }
            uint32_t bfr[4][4];
            #pragma unroll
            for (int j = 0; j < 4; ++j) {
                int row = wn * 64 + j * 16 + lr + (lg >> 1) * 8;
                int kb = t * 32 + (lg & 1) * 16;
                ldm_x4(bfr[j], stB(s) + SMEM_SWIZZLE_128B((uint32_t)(row * 128 + kb)));
            }
            #pragma unroll
            for (int i = 0; i < 2; ++i)
                #pragma unroll
                for (int j = 0; j < 4; ++j) {
                    mma_f16(acc[i][2 * j],     af[i], bfr[j][0], bfr[j][1]);
                    mma_f16(acc[i][2 * j + 1], af[i], bfr[j][2], bfr[j][3]);
                }
        }
    };

    issueLoads(0, 0);
    commitLoads(0, 0);
    __syncthreads();

    for (int c = 0; c < NCHUNK; ++c) {
        const int cur = c & 1, nxt = (c + 1) & 1;
        if (c + 1 < NCHUNK) issueLoads(c + 1, nxt);
        computeChunk(cur);
        if (c + 1 < NCHUNK) commitLoads(c + 1, nxt);
        __syncthreads();
    }

    // ---- epilogue: add fp16 partial, relu, store ----
    const int qm = lane >> 2;
    const int qn = (lane & 3) * 2;
    #pragma unroll
    for (int i = 0; i < 2; ++i) {
        #pragma unroll
        for (int j = 0; j < 8; ++j) {
            int m0 = rowBase + wm * 32 + i * 16;
            int n  = wn * 64 + j * 8 + qn;
            int r0 = m0 + qm, r1 = m0 + 8 + qm;
            if (r0 < B_NODES) {
                __half2 p = *(const __half2*)(g_partial16 + (size_t)r0 * D_DIM + n);
                float2 pf = __half22float2(p);
                float c0 = fmaxf(acc[i][j][0] + pf.x, 0.f);
                float c1 = fmaxf(acc[i][j][1] + pf.y, 0.f);
                *(float2*)(outp + (size_t)r0 * D_DIM + n) = make_float2(c0, c1);
            }
            if (r1 < B_NODES) {
                __half2 p = *(const __half2*)(g_partial16 + (size_t)r1 * D_DIM + n);
                float2 pf = __half22float2(p);
                float c2 = fmaxf(acc[i][j][2] + pf.x, 0.f);
                float c3 = fmaxf(acc[i][j][3] + pf.y, 0.f);
                *(float2*)(outp + (size_t)r1 * D_DIM + n) = make_float2(c2, c3);
            }
        }
    }
}

// ---------------------------------------------------------------------------
// Launch
// Inputs: 0=feats_batch 1=feats_neigh 2=neigh_feats 3=W 4=a 5=Wd 6=edge_src 7=edge_dst
// ---------------------------------------------------------------------------
extern "C" void kernel_launch(void* const* d_in, const int* in_sizes, int n_in,
                              void* d_out, int out_size)
{
    const float* fb   = (const float*)d_in[0];
    const float* fn   = (const float*)d_in[1];
    const float* nf   = (const float*)d_in[2];
    const float* W    = (const float*)d_in[3];
    const float* avec = (const float*)d_in[4];
    const float* Wd   = (const float*)d_in[5];
    const int* edge_dst = (const int*)d_in[7];
    float* out = (float*)d_out;
    (void)in_sizes; (void)n_in; (void)out_size;

    const int SMEM_FUSED = 82944;   // 2 x 40KB + 1KB align slack
    const int SMEM_STD   = 66560;   // 2 x 32KB + 1KB align slack
    cudaFuncSetAttribute(fused_fb_kernel, cudaFuncAttributeMaxDynamicSharedMemorySize, SMEM_FUSED);
    cudaFuncSetAttribute(neigh_kernel,    cudaFuncAttributeMaxDynamicSharedMemorySize, SMEM_STD);
    cudaFuncSetAttribute(gemm2_kernel,    cudaFuncAttributeMaxDynamicSharedMemorySize, SMEM_STD);

    // 0) weight converts + zero s
    convertW_kernel<1><<<(F_DIM * D_DIM + 255) / 256, 256>>>(W);
    convertW_kernel<2><<<(KOUT * D_DIM + 255) / 256, 256>>>(Wd);
    zero_s_kernel<<<(NTOT + 255) / 256, 256>>>();

    // 1) fused fb pass: s[0:B] + partial = fb@Wd[0:512] (fb read ONCE)
    fused_fb_kernel<<<(B_NODES + 63) / 64, 256, SMEM_FUSED>>>(fb, avec);

    // 2) neighbor pass: s[B:] + h16 = fn@W
    neigh_kernel<<<(U_NODES + 127) / 128, 256, SMEM_STD>>>(fn, avec);

    // 3) aggregation -> fp16 h'
    agg_kernel<<<B_NODES, 128>>>(edge_dst);

    // 4) out = relu(partial + [h'|nf]@Wd[512:])
    gemm2_kernel<<<(B_NODES + 127) / 128, 256, SMEM_STD>>>(nf, out);
}

// round 13
// speedup vs baseline: 1.0562x; 1.0480x over previous
#include <cuda_runtime.h>
#include <cuda_fp16.h>
#include <cstdint>

// Problem constants
#define B_NODES 100000
#define U_NODES 50000
#define NTOT    150000
#define F_DIM   512
#define D_DIM   128
#define K_NEIGH 10
#define KOUT    1152

#define SMEM_SWIZZLE_128B(byte_offset) ((byte_offset) ^ (((byte_offset) >> 3) & 0x70))

// ---------------------------------------------------------------------------
// Warp-level tensor-core primitives
// ---------------------------------------------------------------------------
__device__ __forceinline__ uint32_t smem_u32(const void* p) {
    uint32_t a;
    asm("{ .reg .u64 t; cvta.to.shared.u64 t, %1; cvt.u32.u64 %0, t; }" : "=r"(a) : "l"(p));
    return a;
}

__device__ __forceinline__ void ldm_x4(uint32_t* r, uint32_t addr) {
    asm volatile("ldmatrix.sync.aligned.m8n8.x4.shared.b16 {%0,%1,%2,%3}, [%4];"
        : "=r"(r[0]), "=r"(r[1]), "=r"(r[2]), "=r"(r[3]) : "r"(addr));
}

__device__ __forceinline__ void mma_f16(float* c, const uint32_t* a,
                                        uint32_t b0, uint32_t b1) {
    asm volatile("mma.sync.aligned.m16n8k16.row.col.f32.f16.f16.f32 "
        "{%0,%1,%2,%3}, {%4,%5,%6,%7}, {%8,%9}, {%0,%1,%2,%3};"
        : "+f"(c[0]), "+f"(c[1]), "+f"(c[2]), "+f"(c[3])
        : "r"(a[0]), "r"(a[1]), "r"(a[2]), "r"(a[3]), "r"(b0), "r"(b1));
}

__device__ __forceinline__ uint32_t pack_h2(float x, float y) {
    __half2 h = __float22half2_rn(make_float2(x, y));
    return *reinterpret_cast<uint32_t*>(&h);
}

__device__ __forceinline__ void cp_async16(uint32_t dst, const void* src) {
    asm volatile("cp.async.cg.shared.global [%0], [%1], 16;" :: "r"(dst), "l"(src) : "memory");
}
#define CP_ASYNC_COMMIT() asm volatile("cp.async.commit_group;" ::: "memory")
#define CP_ASYNC_WAIT0()  asm volatile("cp.async.wait_group 0;" ::: "memory")

#define STS128(a0, a1, a2, a3, addr) \
    asm volatile("st.shared.v4.b32 [%0], {%1, %2, %3, %4};" \
        :: "r"(addr), "r"(a0), "r"(a1), "r"(a2), "r"(a3) : "memory")

// ---------------------------------------------------------------------------
// Device-global scratch (device-code references only)
// ---------------------------------------------------------------------------
__device__ float g_s[NTOT];
// fp16 h for NEIGHBOR rows only, [U][128]
__device__ __align__(16) __half g_h16[(size_t)U_NODES * D_DIM];
// fp16 h' [B+pad][128] (pad rows never written: stay zero; covers cp.async OOB)
__device__ __align__(16) __half g_hprime16[(size_t)(B_NODES + 256) * D_DIM];
// fp16 partial = fb @ Wd[0:512]  [B][128]
__device__ __align__(16) __half g_partial16[(size_t)B_NODES * D_DIM];
// fp16 transposed weights: [N=128][K]
__device__ __align__(16) __half g_W16_1[(size_t)D_DIM * F_DIM];
__device__ __align__(16) __half g_W16_2[(size_t)D_DIM * KOUT];

// ---------------------------------------------------------------------------
// Weight transpose + fp16 rounding: src [K][128] fp32 -> dstT [128][K] fp16
// ---------------------------------------------------------------------------
template <int WHICH>   // 1 = W (K=512), 2 = Wd (K=1152)
__global__ void convertW_kernel(const float* __restrict__ src)
{
    constexpr int K = (WHICH == 1) ? F_DIM : KOUT;
    __half* dstT = (WHICH == 1) ? g_W16_1 : g_W16_2;

    int idx = blockIdx.x * blockDim.x + threadIdx.x;
    if (idx >= K * D_DIM) return;
    int k = idx >> 7, n = idx & 127;
    dstT[(size_t)n * K + k] = __float2half_rn(src[idx]);
}

// ---------------------------------------------------------------------------
// FB pass: out-cols = [W | Wd[0:512]] concatenated -> N=256 GEMM, K=512.
// 128x256 CTA tile, BK=64, 512 threads (16 warps, 4Mx4N, warp tile 32x64),
// 2-stage pipeline, smem 2 x (A 16KB + B 32KB) = 96KB, 1 CTA/SM.
// Epilogue: cols [0,128) -> s-dot (smem-reduced, plain store);
//           cols [128,256) -> fp16 partial store.
// ---------------------------------------------------------------------------
__global__ void __launch_bounds__(512, 1)
fb_kernel(const float* __restrict__ fb, const float* __restrict__ avec)
{
    constexpr int NCHUNK = F_DIM / 64;   // 8

    extern __shared__ char dsm[];
    const uint32_t ab = (smem_u32(dsm) + 1023u) & ~1023u;

    const int tid = threadIdx.x;
    const int lane = tid & 31;
    const int wid = tid >> 5;        // 0..15
    const int wm = wid & 3;          // M group (4 x 32 rows)
    const int wn = wid >> 2;         // N group (4 x 64 cols)
    const int rowBase = blockIdx.x * 128;

    float acc[2][8][4];
    #pragma unroll
    for (int i = 0; i < 2; ++i)
        #pragma unroll
        for (int j = 0; j < 8; ++j)
            #pragma unroll
            for (int q = 0; q < 4; ++q) acc[i][j][q] = 0.f;

    const int lr = lane & 7;
    const int lg = lane >> 3;

    float4 sa0[2], sa1[2];   // A: 128 rows x 8 segs = 1024 tasks / 512 thr

    auto stA = [&](int s) { return ab + (uint32_t)s * 49152u; };
    auto stB = [&](int s) { return ab + (uint32_t)s * 49152u + 16384u; };

    auto issueLoads = [&](int c, int s) {
        const int k0c = c * 64;
        #pragma unroll
        for (int i = 0; i < 2; ++i) {
            int idx = tid + i * 512;           // 0..1023
            int row = idx >> 3, seg = idx & 7;
            int grow = rowBase + row;
            sa0[i] = make_float4(0.f, 0.f, 0.f, 0.f);
            sa1[i] = sa0[i];
            if (grow < B_NODES) {
                const float* src = fb + (size_t)grow * F_DIM + k0c + seg * 8;
                sa0[i] = *(const float4*)(src);
                sa1[i] = *(const float4*)(src + 4);
            }
        }
        // B tile: 256 n-rows x 8 segs = 2048 tasks / 512 thr
        #pragma unroll
        for (int i = 0; i < 4; ++i) {
            int idx = tid + i * 512;
            int row = idx >> 3, seg = idx & 7;  // row 0..255
            uint32_t off = SMEM_SWIZZLE_128B((uint32_t)(row * 128 + seg * 16));
            const __half* src = (row < 128)
                ? g_W16_1 + (size_t)row * F_DIM + k0c + seg * 8
                : g_W16_2 + (size_t)(row - 128) * KOUT + k0c + seg * 8;
            cp_async16(stB(s) + off, src);
        }
        CP_ASYNC_COMMIT();
    };

    auto commitLoads = [&](int s) {
        #pragma unroll
        for (int i = 0; i < 2; ++i) {
            int idx = tid + i * 512;
            int row = idx >> 3, seg = idx & 7;
            uint32_t w0 = pack_h2(sa0[i].x, sa0[i].y);
            uint32_t w1 = pack_h2(sa0[i].z, sa0[i].w);
            uint32_t w2 = pack_h2(sa1[i].x, sa1[i].y);
            uint32_t w3 = pack_h2(sa1[i].z, sa1[i].w);
            uint32_t off = SMEM_SWIZZLE_128B((uint32_t)(row * 128 + seg * 16));
            STS128(w0, w1, w2, w3, stA(s) + off);
        }
        CP_ASYNC_WAIT0();
    };

    auto computeChunk = [&](int s) {
        #pragma unroll
        for (int t = 0; t < 4; ++t) {
            uint32_t af[2][4];
            #pragma unroll
            for (int i = 0; i < 2; ++i) {
                int row = wm * 32 + i * 16 + lr + (lg & 1) * 8;   // <= 127
                int kb = t * 32 + (lg >> 1) * 16;
                ldm_x4(af[i], stA(s) + SMEM_SWIZZLE_128B((uint32_t)(row * 128 + kb)));
            }
            uint32_t bfr[4][4];
            #pragma unroll
            for (int j = 0; j < 4; ++j) {
                int row = wn * 64 + j * 16 + lr + (lg >> 1) * 8;  // <= 255
                int kb = t * 32 + (lg & 1) * 16;
                ldm_x4(bfr[j], stB(s) + SMEM_SWIZZLE_128B((uint32_t)(row * 128 + kb)));
            }
            #pragma unroll
            for (int i = 0; i < 2; ++i)
                #pragma unroll
                for (int j = 0; j < 4; ++j) {
                    mma_f16(acc[i][2 * j],     af[i], bfr[j][0], bfr[j][1]);
                    mma_f16(acc[i][2 * j + 1], af[i], bfr[j][2], bfr[j][3]);
                }
        }
    };

    issueLoads(0, 0);
    commitLoads(0);
    __syncthreads();

    for (int c = 0; c < NCHUNK; ++c) {
        const int cur = c & 1, nxt = (c + 1) & 1;
        if (c + 1 < NCHUNK) issueLoads(c + 1, nxt);
        computeChunk(cur);
        if (c + 1 < NCHUNK) commitLoads(nxt);
        __syncthreads();
    }

    // ---- epilogue ----
    const int qm = lane >> 2;
    const int qn = (lane & 3) * 2;

    // smem s-buffer (pipeline fully drained; safe to reuse dsm)
    float* s_sm = (float*)dsm;
    if (tid < 128) s_sm[tid] = 0.f;
    __syncthreads();

    if (wn < 2) {
        // W product: s-dot with a[0:128] (fb rows)
        #pragma unroll
        for (int i = 0; i < 2; ++i) {
            int m0 = wm * 32 + i * 16;
            float s0 = 0.f, s1 = 0.f;
            #pragma unroll
            for (int j = 0; j < 8; ++j) {
                int n = wn * 64 + j * 8 + qn;
                s0 += acc[i][j][0] * avec[n] + acc[i][j][1] * avec[n + 1];
                s1 += acc[i][j][2] * avec[n] + acc[i][j][3] * avec[n + 1];
            }
            s0 += __shfl_xor_sync(0xffffffffu, s0, 1);
            s0 += __shfl_xor_sync(0xffffffffu, s0, 2);
            s1 += __shfl_xor_sync(0xffffffffu, s1, 1);
            s1 += __shfl_xor_sync(0xffffffffu, s1, 2);
            if ((lane & 3) == 0) {
                atomicAdd(&s_sm[m0 + qm], s0);
                atomicAdd(&s_sm[m0 + 8 + qm], s1);
            }
        }
    } else {
        // Wd product: partial16 store, cols (wn-2)*64 ...
        #pragma unroll
        for (int i = 0; i < 2; ++i) {
            #pragma unroll
            for (int j = 0; j < 8; ++j) {
                int m0 = rowBase + wm * 32 + i * 16;
                int n  = (wn - 2) * 64 + j * 8 + qn;
                int r0 = m0 + qm, r1 = m0 + 8 + qm;
                if (r0 < B_NODES) {
                    __half2 h = __float22half2_rn(make_float2(acc[i][j][0], acc[i][j][1]));
                    *(__half2*)(g_partial16 + (size_t)r0 * D_DIM + n) = h;
                }
                if (r1 < B_NODES) {
                    __half2 h = __float22half2_rn(make_float2(acc[i][j][2], acc[i][j][3]));
                    *(__half2*)(g_partial16 + (size_t)r1 * D_DIM + n) = h;
                }
            }
        }
    }
    __syncthreads();
    if (tid < 128 && rowBase + tid < B_NODES) g_s[rowBase + tid] = s_sm[tid];
}

// ---------------------------------------------------------------------------
// Neighbor pass: h = fn @ W (128x128 CTA tile, BK=64, 256 thr, 2 CTA/SM).
// Epilogue: s[B+r] (smem-reduced, plain store) + fp16 h write.
// ---------------------------------------------------------------------------
__global__ void __launch_bounds__(256, 2)
neigh_kernel(const float* __restrict__ fn, const float* __restrict__ avec)
{
    constexpr int NCHUNK = F_DIM / 64;   // 8

    extern __shared__ char dsm[];
    const uint32_t ab = (smem_u32(dsm) + 1023u) & ~1023u;

    const int tid = threadIdx.x;
    const int lane = tid & 31;
    const int wm = (tid >> 5) & 3;
    const int wn = (tid >> 5) >> 2;
    const int rowBase = blockIdx.x * 128;

    float acc[2][8][4];
    #pragma unroll
    for (int i = 0; i < 2; ++i)
        #pragma unroll
        for (int j = 0; j < 8; ++j)
            #pragma unroll
            for (int q = 0; q < 4; ++q) acc[i][j][q] = 0.f;

    const int lr = lane & 7;
    const int lg = lane >> 3;

    float4 sa0[4], sa1[4];

    auto stA = [&](int s) { return ab + (uint32_t)s * 32768u; };
    auto stB = [&](int s) { return ab + (uint32_t)s * 32768u + 16384u; };

    auto issueLoads = [&](int c, int s) {
        const int k0c = c * 64;
        #pragma unroll
        for (int i = 0; i < 4; ++i) {
            int idx = tid + i * 256;
            int row = idx >> 3, seg = idx & 7;
            int grow = rowBase + row;
            sa0[i] = make_float4(0.f, 0.f, 0.f, 0.f);
            sa1[i] = sa0[i];
            if (grow < U_NODES) {
                const float* src = fn + (size_t)grow * F_DIM + k0c + seg * 8;
                sa0[i] = *(const float4*)(src);
                sa1[i] = *(const float4*)(src + 4);
            }
        }
        #pragma unroll
        for (int i = 0; i < 4; ++i) {
            int idx = tid + i * 256;
            int row = idx >> 3, seg = idx & 7;
            uint32_t off = SMEM_SWIZZLE_128B((uint32_t)(row * 128 + seg * 16));
            cp_async16(stB(s) + off, g_W16_1 + (size_t)row * F_DIM + k0c + seg * 8);
        }
        CP_ASYNC_COMMIT();
    };

    auto commitLoads = [&](int s) {
        #pragma unroll
        for (int i = 0; i < 4; ++i) {
            int idx = tid + i * 256;
            int row = idx >> 3, seg = idx & 7;
            uint32_t w0 = pack_h2(sa0[i].x, sa0[i].y);
            uint32_t w1 = pack_h2(sa0[i].z, sa0[i].w);
            uint32_t w2 = pack_h2(sa1[i].x, sa1[i].y);
            uint32_t w3 = pack_h2(sa1[i].z, sa1[i].w);
            uint32_t off = SMEM_SWIZZLE_128B((uint32_t)(row * 128 + seg * 16));
            STS128(w0, w1, w2, w3, stA(s) + off);
        }
        CP_ASYNC_WAIT0();
    };

    auto computeChunk = [&](int s) {
        #pragma unroll
        for (int t = 0; t < 4; ++t) {
            uint32_t af[2][4];
            #pragma unroll
            for (int i = 0; i < 2; ++i) {
                int row = wm * 32 + i * 16 + lr + (lg & 1) * 8;
                int kb = t * 32 + (lg >> 1) * 16;
                ldm_x4(af[i], stA(s) + SMEM_SWIZZLE_128B((uint32_t)(row * 128 + kb)));
            }
            uint32_t bfr[4][4];
            #pragma unroll
            for (int j = 0; j < 4; ++j) {
                int row = wn * 64 + j * 16 + lr + (lg >> 1) * 8;
                int kb = t * 32 + (lg & 1) * 16;
                ldm_x4(bfr[j], stB(s) + SMEM_SWIZZLE_128B((uint32_t)(row * 128 + kb)));
            }
            #pragma unroll
            for (int i = 0; i < 2; ++i)
                #pragma unroll
                for (int j = 0; j < 4; ++j) {
                    mma_f16(acc[i][2 * j],     af[i], bfr[j][0], bfr[j][1]);
                    mma_f16(acc[i][2 * j + 1], af[i], bfr[j][2], bfr[j][3]);
                }
        }
    };

    issueLoads(0, 0);
    commitLoads(0);
    __syncthreads();

    for (int c = 0; c < NCHUNK; ++c) {
        const int cur = c & 1, nxt = (c + 1) & 1;
        if (c + 1 < NCHUNK) issueLoads(c + 1, nxt);
        computeChunk(cur);
        if (c + 1 < NCHUNK) commitLoads(nxt);
        __syncthreads();
    }

    // ---- epilogue: smem-reduced s (a[128:256]) + fp16 h ----
    const int qm = lane >> 2;
    const int qn = (lane & 3) * 2;
    const float* av = avec + D_DIM;

    float* s_sm = (float*)dsm;
    if (tid < 128) s_sm[tid] = 0.f;
    __syncthreads();

    #pragma unroll
    for (int i = 0; i < 2; ++i) {
        int m0 = wm * 32 + i * 16;
        int r0 = rowBase + m0 + qm, r1 = rowBase + m0 + 8 + qm;
        float s0 = 0.f, s1 = 0.f;
        #pragma unroll
        for (int j = 0; j < 8; ++j) {
            int n = wn * 64 + j * 8 + qn;
            float c0 = acc[i][j][0], c1 = acc[i][j][1];
            float c2 = acc[i][j][2], c3 = acc[i][j][3];
            s0 += c0 * av[n] + c1 * av[n + 1];
            s1 += c2 * av[n] + c3 * av[n + 1];
            if (r0 < U_NODES) {
                __half2 h = __float22half2_rn(make_float2(c0, c1));
                *(__half2*)(g_h16 + (size_t)r0 * D_DIM + n) = h;
            }
            if (r1 < U_NODES) {
                __half2 h = __float22half2_rn(make_float2(c2, c3));
                *(__half2*)(g_h16 + (size_t)r1 * D_DIM + n) = h;
            }
        }
        s0 += __shfl_xor_sync(0xffffffffu, s0, 1);
        s0 += __shfl_xor_sync(0xffffffffu, s0, 2);
        s1 += __shfl_xor_sync(0xffffffffu, s1, 1);
        s1 += __shfl_xor_sync(0xffffffffu, s1, 2);
        if ((lane & 3) == 0) {
            atomicAdd(&s_sm[m0 + qm], s0);
            atomicAdd(&s_sm[m0 + 8 + qm], s1);
        }
    }
    __syncthreads();
    if (tid < 128 && rowBase + tid < U_NODES)
        g_s[B_NODES + rowBase + tid] = s_sm[tid];
}

// ---------------------------------------------------------------------------
// Aggregation: 4 nodes per block, 64 threads/node, half2 columns.
// ---------------------------------------------------------------------------
__global__ void __launch_bounds__(256) agg_kernel(const int* __restrict__ edge_dst)
{
    const int g  = threadIdx.x >> 6;          // node slot 0..3
    const int t2 = threadIdx.x & 63;          // half2 column
    const int i  = blockIdx.x * 4 + g;

    __shared__ float w[4][K_NEIGH];
    __shared__ int   jj[4][K_NEIGH];
    if (i < B_NODES && t2 < K_NEIGH) {
        int j = edge_dst[(size_t)i * K_NEIGH + t2];
        float sc = g_s[i] + g_s[B_NODES + j];
        float lr = sc > 0.f ? sc : 0.2f * sc;   // leaky_relu, alpha=0.2
        w[g][t2]  = expf(-lr);
        jj[g][t2] = j;
    }
    __syncthreads();
    if (i >= B_NODES) return;

    float ax = 0.f, ay = 0.f, tot = 0.f;
    #pragma unroll
    for (int k = 0; k < K_NEIGH; ++k) {
        float wk = w[g][k];
        tot += wk;
        __half2 hv = *(const __half2*)(g_h16 + (size_t)jj[g][k] * D_DIM + t2 * 2);
        float2 f = __half22float2(hv);
        ax += wk * f.x;
        ay += wk * f.y;
    }
    float vx = ax / tot, vy = ay / tot;
    if (!isfinite(vx)) vx = 0.f;
    if (!isfinite(vy)) vy = 0.f;
    *(__half2*)(g_hprime16 + (size_t)i * D_DIM + t2 * 2) =
        __float22half2_rn(make_float2(vx, vy));
}

// ---------------------------------------------------------------------------
// GEMM2': out = relu(partial + [h'|nf] @ Wd[512:1152])  (K=640, 10 chunks)
// 128x128 CTA tile, BK=64, 2-stage, 2 CTA/SM.
// ---------------------------------------------------------------------------
__global__ void __launch_bounds__(256, 2)
gemm2_kernel(const float* __restrict__ nf, float* __restrict__ outp)
{
    constexpr int NCHUNK = 10;

    extern __shared__ char dsm[];
    const uint32_t ab = (smem_u32(dsm) + 1023u) & ~1023u;

    const int tid = threadIdx.x;
    const int lane = tid & 31;
    const int wm = (tid >> 5) & 3;
    const int wn = (tid >> 5) >> 2;
    const int rowBase = blockIdx.x * 128;

    float acc[2][8][4];
    #pragma unroll
    for (int i = 0; i < 2; ++i)
        #pragma unroll
        for (int j = 0; j < 8; ++j)
            #pragma unroll
            for (int q = 0; q < 4; ++q) acc[i][j][q] = 0.f;

    const int lr = lane & 7;
    const int lg = lane >> 3;

    float4 sa0[4], sa1[4];

    auto stA = [&](int s) { return ab + (uint32_t)s * 32768u; };
    auto stB = [&](int s) { return ab + (uint32_t)s * 32768u + 16384u; };

    auto issueLoads = [&](int c, int s) {
        const int k0 = 512 + c * 64;
        if (c < 2) {
            #pragma unroll
            for (int i = 0; i < 4; ++i) {
                int idx = tid + i * 256;
                int row = idx >> 3, seg = idx & 7;
                int grow = rowBase + row;
                uint32_t off = SMEM_SWIZZLE_128B((uint32_t)(row * 128 + seg * 16));
                cp_async16(stA(s) + off,
                           g_hprime16 + (size_t)grow * D_DIM + (k0 - 512) + seg * 8);
            }
        } else {
            #pragma unroll
            for (int i = 0; i < 4; ++i) {
                int idx = tid + i * 256;
                int row = idx >> 3, seg = idx & 7;
                int grow = rowBase + row;
                sa0[i] = make_float4(0.f, 0.f, 0.f, 0.f);
                sa1[i] = sa0[i];
                if (grow < B_NODES) {
                    const float* src = nf + (size_t)grow * F_DIM + (k0 - 640) + seg * 8;
                    sa0[i] = *(const float4*)(src);
                    sa1[i] = *(const float4*)(src + 4);
                }
            }
        }
        #pragma unroll
        for (int i = 0; i < 4; ++i) {
            int idx = tid + i * 256;
            int row = idx >> 3, seg = idx & 7;
            uint32_t off = SMEM_SWIZZLE_128B((uint32_t)(row * 128 + seg * 16));
            cp_async16(stB(s) + off, g_W16_2 + (size_t)row * KOUT + k0 + seg * 8);
        }
        CP_ASYNC_COMMIT();
    };

    auto commitLoads = [&](int c, int s) {
        if (c >= 2) {
            #pragma unroll
            for (int i = 0; i < 4; ++i) {
                int idx = tid + i * 256;
                int row = idx >> 3, seg = idx & 7;
                uint32_t w0 = pack_h2(sa0[i].x, sa0[i].y);
                uint32_t w1 = pack_h2(sa0[i].z, sa0[i].w);
                uint32_t w2 = pack_h2(sa1[i].x, sa1[i].y);
                uint32_t w3 = pack_h2(sa1[i].z, sa1[i].w);
                uint32_t off = SMEM_SWIZZLE_128B((uint32_t)(row * 128 + seg * 16));
                STS128(w0, w1, w2, w3, stA(s) + off);
            }
        }
        CP_ASYNC_WAIT0();
    };

    auto computeChunk = [&](int s) {
        #pragma unroll
        for (int t = 0; t < 4; ++t) {
            uint32_t af[2][4];
            #pragma unroll
            for (int i = 0; i < 2; ++i) {
                int row = wm * 32 + i * 16 + lr + (lg & 1) * 8;
                int kb = t * 32 + (lg >> 1) * 16;
                ldm_x4(af[i], stA(s) + SMEM_SWIZZLE_128B((uint32_t)(row * 128 + kb)));
            }
            uint32_t bfr[4][4];
            #pragma unroll
            for (int j = 0; j < 4; ++j) {
                int row = wn * 64 + j * 16 + lr + (lg >> 1) * 8;
                int kb = t * 32 + (lg & 1) * 16;
                ldm_x4(bfr[j], stB(s) + SMEM_SWIZZLE_128B((uint32_t)(row * 128 + kb)));
            }
            #pragma unroll
            for (int i = 0; i < 2; ++i)
                #pragma unroll
                for (int j = 0; j < 4; ++j) {
                    mma_f16(acc[i][2 * j],     af[i], bfr[j][0], bfr[j][1]);
                    mma_f16(acc[i][2 * j + 1], af[i], bfr[j][2], bfr[j][3]);
                }
        }
    };

    issueLoads(0, 0);
    commitLoads(0, 0);
    __syncthreads();

    for (int c = 0; c < NCHUNK; ++c) {
        const int cur = c & 1, nxt = (c + 1) & 1;
        if (c + 1 < NCHUNK) issueLoads(c + 1, nxt);
        computeChunk(cur);
        if (c + 1 < NCHUNK) commitLoads(c + 1, nxt);
        __syncthreads();
    }

    // ---- epilogue: add fp16 partial, relu, store ----
    const int qm = lane >> 2;
    const int qn = (lane & 3) * 2;
    #pragma unroll
    for (int i = 0; i < 2; ++i) {
        #pragma unroll
        for (int j = 0; j < 8; ++j) {
            int m0 = rowBase + wm * 32 + i * 16;
            int n  = wn * 64 + j * 8 + qn;
            int r0 = m0 + qm, r1 = m0 + 8 + qm;
            if (r0 < B_NODES) {
                __half2 p = *(const __half2*)(g_partial16 + (size_t)r0 * D_DIM + n);
                float2 pf = __half22float2(p);
                float c0 = fmaxf(acc[i][j][0] + pf.x, 0.f);
                float c1 = fmaxf(acc[i][j][1] + pf.y, 0.f);
                *(float2*)(outp + (size_t)r0 * D_DIM + n) = make_float2(c0, c1);
            }
            if (r1 < B_NODES) {
                __half2 p = *(const __half2*)(g_partial16 + (size_t)r1 * D_DIM + n);
                float2 pf = __half22float2(p);
                float c2 = fmaxf(acc[i][j][2] + pf.x, 0.f);
                float c3 = fmaxf(acc[i][j][3] + pf.y, 0.f);
                *(float2*)(outp + (size_t)r1 * D_DIM + n) = make_float2(c2, c3);
            }
        }
    }
}

// ---------------------------------------------------------------------------
// Launch
// Inputs: 0=feats_batch 1=feats_neigh 2=neigh_feats 3=W 4=a 5=Wd 6=edge_src 7=edge_dst
// ---------------------------------------------------------------------------
extern "C" void kernel_launch(void* const* d_in, const int* in_sizes, int n_in,
                              void* d_out, int out_size)
{
    const float* fb   = (const float*)d_in[0];
    const float* fn   = (const float*)d_in[1];
    const float* nf   = (const float*)d_in[2];
    const float* W    = (const float*)d_in[3];
    const float* avec = (const float*)d_in[4];
    const float* Wd   = (const float*)d_in[5];
    const int* edge_dst = (const int*)d_in[7];
    float* out = (float*)d_out;
    (void)in_sizes; (void)n_in; (void)out_size;

    const int SMEM_FB  = 99328;   // 2 x 48KB stages + 1KB align slack
    const int SMEM_STD = 66560;   // 2 x 32KB stages + 1KB align slack
    cudaFuncSetAttribute(fb_kernel,    cudaFuncAttributeMaxDynamicSharedMemorySize, SMEM_FB);
    cudaFuncSetAttribute(neigh_kernel, cudaFuncAttributeMaxDynamicSharedMemorySize, SMEM_STD);
    cudaFuncSetAttribute(gemm2_kernel, cudaFuncAttributeMaxDynamicSharedMemorySize, SMEM_STD);

    // 0) weight converts
    convertW_kernel<1><<<(F_DIM * D_DIM + 255) / 256, 256>>>(W);
    convertW_kernel<2><<<(KOUT * D_DIM + 255) / 256, 256>>>(Wd);

    // 1) fb pass: N=256 concat GEMM -> s[0:B] + partial16 (fb read once)
    fb_kernel<<<(B_NODES + 127) / 128, 512, SMEM_FB>>>(fb, avec);

    // 2) neighbor pass: s[B:] + h16 = fn@W
    neigh_kernel<<<(U_NODES + 127) / 128, 256, SMEM_STD>>>(fn, avec);

    // 3) aggregation -> fp16 h'
    agg_kernel<<<(B_NODES + 3) / 4, 256>>>(edge_dst);

    // 4) out = relu(partial + [h'|nf]@Wd[512:])
    gemm2_kernel<<<(B_NODES + 127) / 128, 256, SMEM_STD>>>(nf, out);
}